// round 9
// baseline (speedup 1.0000x reference)
#include <cuda_runtime.h>
#include <cstdint>
#include <climits>

#define NUM_MASKS 64
#define MH 1024
#define MW 1024
#define NTHREADS 256
#define GRID 1216                          // 152 SMs * 8 blocks, one co-resident wave
#define NWARPS (GRID * 8)                  // 9728 worker warps
#define UINT4_PER_MASK ((MH * MW) / 4)     // 262144
#define UNITS_PER_MASK 256                 // unit = 4 rows = 16KB contiguous
#define NUNITS (NUM_MASKS * UNITS_PER_MASK)  // 16384
#define AREA_THRESH 1024   // (1024/32)*(1024/32); keep = count > AREA_THRESH

// Per-mask accumulators, encoded so ZERO is the correct initial state:
//   g_aminx = max over units of (1023 - minx)   -> minx = 1023 - g_aminx
//   g_aminy = max over units of (1023 - miny)   -> miny = 1023 - g_aminy
//   g_amaxx = max(maxx), g_amaxy = max(maxy)    (only written when pixels exist)
//   g_acnt  = sum(count)
// Finalizer resets its mask's slots to 0 -> every graph replay starts clean.
__device__ unsigned g_aminx[NUM_MASKS];
__device__ unsigned g_aminy[NUM_MASKS];
__device__ unsigned g_amaxx[NUM_MASKS];
__device__ unsigned g_amaxy[NUM_MASKS];
__device__ unsigned g_acnt [NUM_MASKS];
__device__ unsigned g_mdone[NUM_MASKS];
// Work-stealing counter (starts after the static prefix) and warp-done counter.
__device__ unsigned g_unit  = NWARPS;
__device__ unsigned g_wdone = 0;

__global__ __launch_bounds__(NTHREADS, 8) void fsam_fused_kernel(
    const float* __restrict__ masks, float* __restrict__ out) {

    const int tid  = threadIdx.x;
    const int wid  = tid >> 5;
    const int lane = tid & 31;

    const uint4* __restrict__ base = reinterpret_cast<const uint4*>(masks);

    unsigned u = (unsigned)(blockIdx.x * 8 + wid);   // static first unit
    unsigned nxt = 0;

    while (u < NUNITS) {
        // Prefetch next unit id; latency hidden under this unit's 32 loads.
        if (lane == 0) nxt = atomicAdd(&g_unit, 1u);

        const int mask = (int)(u >> 8);
        const int rq   = (int)(u & 255u);            // 4-row quad
        const int r0   = rq << 2;
        // Unit = rows [r0, r0+4) of this mask = 16KB contiguous.
        const uint4* __restrict__ p =
            base + (size_t)mask * UINT4_PER_MASK + rq * 1024 + lane;

        int uminx = INT_MAX, umaxx = -1;
        unsigned rowmask = 0u;
        float fc0 = 0.f, fc1 = 0.f, fc2 = 0.f, fc3 = 0.f;

        // seg-major: thread column constant within a segment -> one ffs/clz per seg.
        #pragma unroll
        for (int seg = 0; seg < 8; seg++) {
            uint4 cm = make_uint4(0u, 0u, 0u, 0u);
            #pragma unroll
            for (int ri = 0; ri < 4; ri++) {
                uint4 v = p[seg * 32 + ri * 256];
                cm.x |= v.x; cm.y |= v.y; cm.z |= v.z; cm.w |= v.w;
                unsigned any = (v.x | v.y) | (v.z | v.w);
                rowmask |= (unsigned)(any != 0u) << ri;
                fc0 += __uint_as_float(v.x);
                fc1 += __uint_as_float(v.y);
                fc2 += __uint_as_float(v.z);
                fc3 += __uint_as_float(v.w);
            }
            unsigned mb =  (unsigned)(cm.x != 0u)
                        | ((unsigned)(cm.y != 0u) << 1)
                        | ((unsigned)(cm.z != 0u) << 2)
                        | ((unsigned)(cm.w != 0u) << 3);
            if (mb) {
                const int cb = seg * 128 + (lane << 2);
                uminx = min(uminx, cb + (__ffs(mb) - 1));
                umaxx = max(umaxx, cb + (31 - __clz(mb)));
            }
        }

        int uminy, umaxy;
        if (rowmask) {
            uminy = r0 + (__ffs(rowmask) - 1);
            umaxy = r0 + (31 - __clz(rowmask));
        } else { uminy = INT_MAX; umaxy = -1; }
        int ucnt = (int)((fc0 + fc1) + (fc2 + fc3));

        // Warp reduction (no block barrier anywhere).
        #pragma unroll
        for (int off = 16; off > 0; off >>= 1) {
            uminx = min(uminx, __shfl_down_sync(0xFFFFFFFFu, uminx, off));
            uminy = min(uminy, __shfl_down_sync(0xFFFFFFFFu, uminy, off));
            umaxx = max(umaxx, __shfl_down_sync(0xFFFFFFFFu, umaxx, off));
            umaxy = max(umaxy, __shfl_down_sync(0xFFFFFFFFu, umaxy, off));
            ucnt +=            __shfl_down_sync(0xFFFFFFFFu, ucnt,  off);
        }

        if (lane == 0) {
            if (ucnt > 0) {   // any pixel in unit -> min/max valid
                atomicMax(&g_aminx[mask], (unsigned)(1023 - uminx));
                atomicMax(&g_aminy[mask], (unsigned)(1023 - uminy));
                atomicMax(&g_amaxx[mask], (unsigned)umaxx);
                atomicMax(&g_amaxy[mask], (unsigned)umaxy);
                atomicAdd(&g_acnt [mask], (unsigned)ucnt);
            }
            __threadfence();   // data atomics visible before arrival
            unsigned pos = atomicAdd(&g_mdone[mask], 1u);
            if (pos == UNITS_PER_MASK - 1) {
                __threadfence();   // acquire: all units' merges visible
                unsigned ax = *(volatile unsigned*)&g_aminx[mask];
                unsigned ay = *(volatile unsigned*)&g_aminy[mask];
                unsigned bx = *(volatile unsigned*)&g_amaxx[mask];
                unsigned by = *(volatile unsigned*)&g_amaxy[mask];
                unsigned ct = *(volatile unsigned*)&g_acnt [mask];
                float4 b = (ct > AREA_THRESH)
                    ? make_float4((float)(1023 - (int)ax), (float)(1023 - (int)ay),
                                  (float)bx, (float)by)
                    : make_float4(0.f, 0.f, 0.f, 0.f);
                reinterpret_cast<float4*>(out)[mask] = b;
                // Reset this mask's state for the next graph replay.
                g_aminx[mask] = 0u; g_aminy[mask] = 0u;
                g_amaxx[mask] = 0u; g_amaxy[mask] = 0u;
                g_acnt [mask] = 0u; g_mdone[mask] = 0u;
            }
        }

        u = __shfl_sync(0xFFFFFFFFu, nxt, 0);
    }

    // Warp exit: last warp resets the scheduling counters for replay.
    if (lane == 0) {
        __threadfence();
        unsigned wpos = atomicAdd(&g_wdone, 1u);
        if (wpos == NWARPS - 1) {
            g_unit  = NWARPS;
            g_wdone = 0u;
        }
    }
}

extern "C" void kernel_launch(void* const* d_in, const int* in_sizes, int n_in,
                              void* d_out, int out_size) {
    const float* masks = (const float*)d_in[0];
    float* out = (float*)d_out;
    fsam_fused_kernel<<<GRID, NTHREADS>>>(masks, out);
}

// round 10
// speedup vs baseline: 1.0211x; 1.0211x over previous
#include <cuda_runtime.h>
#include <cstdint>
#include <climits>

#define NUM_MASKS 64
#define MH 1024
#define MW 1024
#define NTHREADS 256
#define BLOCKS_PER_MASK 19
#define GRID (NUM_MASKS * BLOCKS_PER_MASK)   // 1216 = 152 SMs * 8 blocks exactly
#define UINT4_PER_MASK ((MH * MW) / 4)       // 262144
#define STATIC_ROWS 48                       // per block static slab (19*48 = 912)
#define STATIC_TOTAL (BLOCKS_PER_MASK * STATIC_ROWS)  // 912
#define STEAL_ROWS 4                         // steal unit = 4 rows (16KB)
#define NSTEAL ((MH - STATIC_TOTAL) / STEAL_ROWS)     // 28 units per mask
#define AREA_THRESH 1024   // (1024/32)*(1024/32); keep = count > AREA_THRESH

// Per-block partials. Every slot written every launch -> no init needed.
__device__ int g_pminx[GRID];
__device__ int g_pminy[GRID];
__device__ int g_pmaxx[GRID];
__device__ int g_pmaxy[GRID];
__device__ int g_pcnt [GRID];
// Per-mask steal + arrival counters; each mask's finalizer resets both.
__device__ unsigned g_msteal [NUM_MASKS];   // zero-init; unit idx allocator
__device__ unsigned g_marrive[NUM_MASKS];   // zero-init; 19 arrivals/mask

__global__ __launch_bounds__(NTHREADS, 8) void fsam_fused_kernel(
    const float* __restrict__ masks, float* __restrict__ out) {

    const int tid  = threadIdx.x;
    const int wid  = tid >> 5;
    const int lane = tid & 31;
    const int colbase = tid << 2;

    const int mask = blockIdx.x / BLOCKS_PER_MASK;
    const int bsub = blockIdx.x - mask * BLOCKS_PER_MASK;
    const int row0 = bsub * STATIC_ROWS;

    const uint4* __restrict__ mbase =
        reinterpret_cast<const uint4*>(masks) + (size_t)mask * UINT4_PER_MASK;

    // ================= static phase: 48 contiguous rows, R8 streaming ========
    // Thread column constant (tid*4): column-OR accumulates across all chunks.
    uint4 cm = make_uint4(0u, 0u, 0u, 0u);
    int miny = INT_MAX, maxy = -1;
    int minx = INT_MAX, maxx = -1;     // x extremes from the steal phase
    float fc0 = 0.f, fc1 = 0.f, fc2 = 0.f, fc3 = 0.f;

    {
        const uint4* __restrict__ ps = mbase + row0 * 256 + tid;
        #pragma unroll
        for (int k = 0; k < STATIC_ROWS / 8; k++) {
            unsigned rowmask = 0u;
            #pragma unroll
            for (int j = 0; j < 8; j++) {
                uint4 v = ps[(k * 8 + j) * 256];
                cm.x |= v.x; cm.y |= v.y; cm.z |= v.z; cm.w |= v.w;
                unsigned any = (v.x | v.y) | (v.z | v.w);
                rowmask |= (unsigned)(any != 0u) << j;
                fc0 += __uint_as_float(v.x);
                fc1 += __uint_as_float(v.y);
                fc2 += __uint_as_float(v.z);
                fc3 += __uint_as_float(v.w);
            }
            if (rowmask) {
                const int r = row0 + k * 8;
                miny = min(miny, r + (__ffs(rowmask) - 1));
                maxy = max(maxy, r + (31 - __clz(rowmask)));
            }
        }
    }

    // ================= steal phase: warp-level, same mask, no per-unit merge ==
    {
        unsigned idx = 0;
        if (lane == 0) idx = atomicAdd(&g_msteal[mask], 1u);
        idx = __shfl_sync(0xFFFFFFFFu, idx, 0);
        while (idx < NSTEAL) {
            unsigned nxt = 0;
            if (lane == 0) nxt = atomicAdd(&g_msteal[mask], 1u);  // prefetch

            const int r0 = STATIC_TOTAL + (int)idx * STEAL_ROWS;
            const uint4* __restrict__ p = mbase + r0 * 256 + lane;
            unsigned rowmask = 0u;
            // seg-major: lane col = seg*128 + lane*4, constant within seg.
            #pragma unroll
            for (int seg = 0; seg < 8; seg++) {
                uint4 sm4 = make_uint4(0u, 0u, 0u, 0u);
                #pragma unroll
                for (int ri = 0; ri < STEAL_ROWS; ri++) {
                    uint4 v = p[seg * 32 + ri * 256];
                    sm4.x |= v.x; sm4.y |= v.y; sm4.z |= v.z; sm4.w |= v.w;
                    unsigned any = (v.x | v.y) | (v.z | v.w);
                    rowmask |= (unsigned)(any != 0u) << ri;
                    fc0 += __uint_as_float(v.x);
                    fc1 += __uint_as_float(v.y);
                    fc2 += __uint_as_float(v.z);
                    fc3 += __uint_as_float(v.w);
                }
                unsigned mb =  (unsigned)(sm4.x != 0u)
                            | ((unsigned)(sm4.y != 0u) << 1)
                            | ((unsigned)(sm4.z != 0u) << 2)
                            | ((unsigned)(sm4.w != 0u) << 3);
                if (mb) {
                    const int cb = seg * 128 + (lane << 2);
                    minx = min(minx, cb + (__ffs(mb) - 1));
                    maxx = max(maxx, cb + (31 - __clz(mb)));
                }
            }
            if (rowmask) {
                miny = min(miny, r0 + (__ffs(rowmask) - 1));
                maxy = max(maxy, r0 + (31 - __clz(rowmask)));
            }
            idx = __shfl_sync(0xFFFFFFFFu, nxt, 0);
        }
    }

    // ================= merge static x-extent into minx/maxx ==================
    unsigned mbits =  (unsigned)(cm.x != 0u)
                   | ((unsigned)(cm.y != 0u) << 1)
                   | ((unsigned)(cm.z != 0u) << 2)
                   | ((unsigned)(cm.w != 0u) << 3);
    if (mbits) {
        minx = min(minx, colbase + (__ffs(mbits) - 1));
        maxx = max(maxx, colbase + (31 - __clz(mbits)));
    }
    int cnt = (int)((fc0 + fc1) + (fc2 + fc3));

    // ================= single block reduction =================================
    #pragma unroll
    for (int off = 16; off > 0; off >>= 1) {
        minx = min(minx, __shfl_down_sync(0xFFFFFFFFu, minx, off));
        miny = min(miny, __shfl_down_sync(0xFFFFFFFFu, miny, off));
        maxx = max(maxx, __shfl_down_sync(0xFFFFFFFFu, maxx, off));
        maxy = max(maxy, __shfl_down_sync(0xFFFFFFFFu, maxy, off));
        cnt +=           __shfl_down_sync(0xFFFFFFFFu, cnt,  off);
    }

    __shared__ int s_minx[8], s_miny[8], s_maxx[8], s_maxy[8], s_cnt[8];
    if (lane == 0) {
        s_minx[wid] = minx; s_miny[wid] = miny;
        s_maxx[wid] = maxx; s_maxy[wid] = maxy;
        s_cnt [wid] = cnt;
    }
    __syncthreads();

    // Warp 0: publish partial, arrive; 19th block of the mask finalizes.
    if (wid == 0) {
        unsigned pos = 0;
        if (lane == 0) {
            int bminx = s_minx[0], bminy = s_miny[0];
            int bmaxx = s_maxx[0], bmaxy = s_maxy[0];
            int bcnt  = s_cnt[0];
            #pragma unroll
            for (int j = 1; j < NTHREADS / 32; j++) {
                bminx = min(bminx, s_minx[j]);
                bminy = min(bminy, s_miny[j]);
                bmaxx = max(bmaxx, s_maxx[j]);
                bmaxy = max(bmaxy, s_maxy[j]);
                bcnt += s_cnt[j];
            }
            g_pminx[blockIdx.x] = bminx;
            g_pminy[blockIdx.x] = bminy;
            g_pmaxx[blockIdx.x] = bmaxx;
            g_pmaxy[blockIdx.x] = bmaxy;
            g_pcnt [blockIdx.x] = bcnt;
            __threadfence();   // partials visible before arrival
            pos = atomicAdd(&g_marrive[mask], 1u);
        }
        pos = __shfl_sync(0xFFFFFFFFu, pos, 0);

        if (pos == BLOCKS_PER_MASK - 1) {
            __threadfence();   // acquire: all partials of this mask
            int fminx = INT_MAX, fminy = INT_MAX, fmaxx = -1, fmaxy = -1, fcnt = 0;
            if (lane < BLOCKS_PER_MASK) {
                const int idx = mask * BLOCKS_PER_MASK + lane;
                fminx = g_pminx[idx];
                fminy = g_pminy[idx];
                fmaxx = g_pmaxx[idx];
                fmaxy = g_pmaxy[idx];
                fcnt  = g_pcnt [idx];
            }
            #pragma unroll
            for (int off = 16; off > 0; off >>= 1) {
                fminx = min(fminx, __shfl_down_sync(0xFFFFFFFFu, fminx, off));
                fminy = min(fminy, __shfl_down_sync(0xFFFFFFFFu, fminy, off));
                fmaxx = max(fmaxx, __shfl_down_sync(0xFFFFFFFFu, fmaxx, off));
                fmaxy = max(fmaxy, __shfl_down_sync(0xFFFFFFFFu, fmaxy, off));
                fcnt +=            __shfl_down_sync(0xFFFFFFFFu, fcnt,  off);
            }
            if (lane == 0) {
                float4 b = (fcnt > AREA_THRESH)
                    ? make_float4((float)fminx, (float)fminy, (float)fmaxx, (float)fmaxy)
                    : make_float4(0.f, 0.f, 0.f, 0.f);
                reinterpret_cast<float4*>(out)[mask] = b;
                g_msteal [mask] = 0u;   // reset for next graph replay
                g_marrive[mask] = 0u;
            }
        }
    }
}

extern "C" void kernel_launch(void* const* d_in, const int* in_sizes, int n_in,
                              void* d_out, int out_size) {
    const float* masks = (const float*)d_in[0];
    float* out = (float*)d_out;
    fsam_fused_kernel<<<GRID, NTHREADS>>>(masks, out);
}

// round 11
// speedup vs baseline: 1.3275x; 1.3001x over previous
#include <cuda_runtime.h>
#include <cstdint>
#include <climits>

#define NUM_MASKS 64
#define MH 1024
#define MW 1024
#define NTHREADS 256
#define BLOCKS_PER_MASK 19
#define GRID (NUM_MASKS * BLOCKS_PER_MASK)   // 1216 = 152 SMs * 8 blocks exactly
#define UINT4_PER_MASK ((MH * MW) / 4)       // 262144
#define AREA_THRESH 1024   // (1024/32)*(1024/32); keep = count > AREA_THRESH

// Per-block partials. Every slot written every launch -> no init needed.
__device__ int g_pminx[GRID];
__device__ int g_pminy[GRID];
__device__ int g_pmaxx[GRID];
__device__ int g_pmaxy[GRID];
__device__ int g_pcnt [GRID];
// Per-mask arrival counters; each mask's finalizer resets its own counter.
__device__ unsigned int g_marrive[NUM_MASKS];  // zero-initialized once

__global__ __launch_bounds__(NTHREADS, 8) void fsam_fused_kernel(
    const float* __restrict__ masks, float* __restrict__ out) {

    const int tid  = threadIdx.x;
    const int wid  = tid >> 5;
    const int lane = tid & 31;
    const int colbase = tid << 2;

    const int mask = blockIdx.x / BLOCKS_PER_MASK;
    const int bsub = blockIdx.x - mask * BLOCKS_PER_MASK;

    // Contiguous uneven slab: rows [bsub*1024/19, (bsub+1)*1024/19) -> 53 or 54 rows.
    const int row_start = (bsub * MH) / BLOCKS_PER_MASK;
    const int row_end   = ((bsub + 1) * MH) / BLOCKS_PER_MASK;

    const uint4* __restrict__ mbase =
        reinterpret_cast<const uint4*>(masks) + (size_t)mask * UINT4_PER_MASK + tid;

    // Thread column constant (tid*4): column-OR accumulates across everything.
    uint4 cm = make_uint4(0u, 0u, 0u, 0u);
    int miny = INT_MAX, maxy = -1;
    float fc0 = 0.f, fc1 = 0.f, fc2 = 0.f, fc3 = 0.f;

    int r = row_start;
    // Fast path: unrolled 8-row chunks, barrier-free, back-to-back LDG.128,
    // branch-free y-extent fixup (select, no BSSY/BSYNC in the mainloop).
    for (; r + 8 <= row_end; r += 8) {
        const uint4* __restrict__ p = mbase + r * 256;
        unsigned rowmask = 0u;
        #pragma unroll
        for (int j = 0; j < 8; j++) {
            uint4 v = p[j * 256];
            cm.x |= v.x; cm.y |= v.y; cm.z |= v.z; cm.w |= v.w;
            unsigned any = (v.x | v.y) | (v.z | v.w);
            rowmask |= (unsigned)(any != 0u) << j;
            fc0 += __uint_as_float(v.x);
            fc1 += __uint_as_float(v.y);
            fc2 += __uint_as_float(v.z);
            fc3 += __uint_as_float(v.w);
        }
        const int f = __ffs(rowmask);                 // 0 when rowmask == 0
        miny = min(miny, f ? r + f - 1 : INT_MAX);
        maxy = max(maxy, rowmask ? r + (31 - __clz(rowmask)) : -1);
    }
    // Tail: up to 7 single rows, also branch-free.
    for (; r < row_end; r++) {
        uint4 v = mbase[r * 256];
        cm.x |= v.x; cm.y |= v.y; cm.z |= v.z; cm.w |= v.w;
        const bool any = ((v.x | v.y) | (v.z | v.w)) != 0u;
        miny = min(miny, any ? r : INT_MAX);
        maxy = max(maxy, any ? r : -1);
        fc0 += __uint_as_float(v.x);
        fc1 += __uint_as_float(v.y);
        fc2 += __uint_as_float(v.z);
        fc3 += __uint_as_float(v.w);
    }

    int cnt = (int)((fc0 + fc1) + (fc2 + fc3));
    unsigned mbits =  (unsigned)(cm.x != 0u)
                   | ((unsigned)(cm.y != 0u) << 1)
                   | ((unsigned)(cm.z != 0u) << 2)
                   | ((unsigned)(cm.w != 0u) << 3);
    const int fx = __ffs(mbits);
    int minx = fx    ? colbase + fx - 1             : INT_MAX;
    int maxx = mbits ? colbase + (31 - __clz(mbits)) : -1;

    // ---- single block reduction ----
    #pragma unroll
    for (int off = 16; off > 0; off >>= 1) {
        minx = min(minx, __shfl_down_sync(0xFFFFFFFFu, minx, off));
        miny = min(miny, __shfl_down_sync(0xFFFFFFFFu, miny, off));
        maxx = max(maxx, __shfl_down_sync(0xFFFFFFFFu, maxx, off));
        maxy = max(maxy, __shfl_down_sync(0xFFFFFFFFu, maxy, off));
        cnt +=           __shfl_down_sync(0xFFFFFFFFu, cnt,  off);
    }

    __shared__ int s_minx[8], s_miny[8], s_maxx[8], s_maxy[8], s_cnt[8];
    if (lane == 0) {
        s_minx[wid] = minx; s_miny[wid] = miny;
        s_maxx[wid] = maxx; s_maxy[wid] = maxy;
        s_cnt [wid] = cnt;
    }
    __syncthreads();

    // Warp 0: publish partial, arrive on per-mask counter; the 19th block
    // of each mask reduces that mask's partials and writes its bbox.
    if (wid == 0) {
        unsigned pos = 0;
        if (lane == 0) {
            int bminx = s_minx[0], bminy = s_miny[0];
            int bmaxx = s_maxx[0], bmaxy = s_maxy[0];
            int bcnt  = s_cnt[0];
            #pragma unroll
            for (int j = 1; j < NTHREADS / 32; j++) {
                bminx = min(bminx, s_minx[j]);
                bminy = min(bminy, s_miny[j]);
                bmaxx = max(bmaxx, s_maxx[j]);
                bmaxy = max(bmaxy, s_maxy[j]);
                bcnt += s_cnt[j];
            }
            g_pminx[blockIdx.x] = bminx;
            g_pminy[blockIdx.x] = bminy;
            g_pmaxx[blockIdx.x] = bmaxx;
            g_pmaxy[blockIdx.x] = bmaxy;
            g_pcnt [blockIdx.x] = bcnt;
            __threadfence();   // partials visible before arrival
            pos = atomicAdd(&g_marrive[mask], 1u);
        }
        pos = __shfl_sync(0xFFFFFFFFu, pos, 0);

        if (pos == BLOCKS_PER_MASK - 1) {
            __threadfence();   // acquire: see all partials of this mask
            int fminx = INT_MAX, fminy = INT_MAX, fmaxx = -1, fmaxy = -1, fcnt = 0;
            if (lane < BLOCKS_PER_MASK) {
                const int idx = mask * BLOCKS_PER_MASK + lane;
                fminx = g_pminx[idx];
                fminy = g_pminy[idx];
                fmaxx = g_pmaxx[idx];
                fmaxy = g_pmaxy[idx];
                fcnt  = g_pcnt [idx];
            }
            #pragma unroll
            for (int off = 16; off > 0; off >>= 1) {
                fminx = min(fminx, __shfl_down_sync(0xFFFFFFFFu, fminx, off));
                fminy = min(fminy, __shfl_down_sync(0xFFFFFFFFu, fminy, off));
                fmaxx = max(fmaxx, __shfl_down_sync(0xFFFFFFFFu, fmaxx, off));
                fmaxy = max(fmaxy, __shfl_down_sync(0xFFFFFFFFu, fmaxy, off));
                fcnt +=            __shfl_down_sync(0xFFFFFFFFu, fcnt,  off);
            }
            if (lane == 0) {
                float4 b = (fcnt > AREA_THRESH)
                    ? make_float4((float)fminx, (float)fminy, (float)fmaxx, (float)fmaxy)
                    : make_float4(0.f, 0.f, 0.f, 0.f);
                reinterpret_cast<float4*>(out)[mask] = b;
                g_marrive[mask] = 0;   // reset for next graph replay
            }
        }
    }
}

extern "C" void kernel_launch(void* const* d_in, const int* in_sizes, int n_in,
                              void* d_out, int out_size) {
    const float* masks = (const float*)d_in[0];
    float* out = (float*)d_out;
    fsam_fused_kernel<<<GRID, NTHREADS>>>(masks, out);
}

// round 12
// speedup vs baseline: 1.3947x; 1.0506x over previous
#include <cuda_runtime.h>
#include <cstdint>
#include <climits>

#define NUM_MASKS 64
#define MH 1024
#define MW 1024
#define NTHREADS 256
#define BLOCKS_PER_MASK 19
#define GRID (NUM_MASKS * BLOCKS_PER_MASK)   // 1216 = 152 SMs * 8 blocks exactly
#define UINT4_PER_MASK ((MH * MW) / 4)       // 262144
#define AREA_THRESH 1024   // (1024/32)*(1024/32); keep = count > AREA_THRESH

// Per-block partials. Every slot written every launch -> no init needed.
__device__ int g_pminx[GRID];
__device__ int g_pminy[GRID];
__device__ int g_pmaxx[GRID];
__device__ int g_pmaxy[GRID];
__device__ int g_pcnt [GRID];
// Per-mask arrival counters; each mask's finalizer resets its own counter.
__device__ unsigned int g_marrive[NUM_MASKS];  // zero-initialized once

__global__ __launch_bounds__(NTHREADS, 8) void fsam_fused_kernel(
    const float* __restrict__ masks, float* __restrict__ out) {

    const int tid  = threadIdx.x;
    const int wid  = tid >> 5;
    const int lane = tid & 31;
    const int colbase = tid << 2;

    const int mask = blockIdx.x / BLOCKS_PER_MASK;
    const int bsub = blockIdx.x - mask * BLOCKS_PER_MASK;

    // Contiguous uneven slab: rows [bsub*1024/19, (bsub+1)*1024/19) -> 53 or 54 rows.
    const int row_start = (bsub * MH) / BLOCKS_PER_MASK;
    const int row_end   = ((bsub + 1) * MH) / BLOCKS_PER_MASK;

    const uint4* __restrict__ mbase =
        reinterpret_cast<const uint4*>(masks) + (size_t)mask * UINT4_PER_MASK + tid;

    // Thread column constant (tid*4): column-OR accumulates across everything.
    uint4 cm = make_uint4(0u, 0u, 0u, 0u);
    int miny = INT_MAX, maxy = -1;
    float fc0 = 0.f, fc1 = 0.f, fc2 = 0.f, fc3 = 0.f;

    int r = row_start;
    // Fast path: unrolled 8-row chunks, barrier-free, back-to-back LDG.128.
    for (; r + 8 <= row_end; r += 8) {
        const uint4* __restrict__ p = mbase + r * 256;
        unsigned rowmask = 0u;
        #pragma unroll
        for (int j = 0; j < 8; j++) {
            uint4 v = p[j * 256];
            cm.x |= v.x; cm.y |= v.y; cm.z |= v.z; cm.w |= v.w;
            unsigned any = (v.x | v.y) | (v.z | v.w);
            rowmask |= (unsigned)(any != 0u) << j;
            fc0 += __uint_as_float(v.x);
            fc1 += __uint_as_float(v.y);
            fc2 += __uint_as_float(v.z);
            fc3 += __uint_as_float(v.w);
        }
        if (rowmask) {
            miny = min(miny, r + (__ffs(rowmask) - 1));
            maxy = max(maxy, r + (31 - __clz(rowmask)));
        }
    }
    // Tail: up to 7 single rows.
    for (; r < row_end; r++) {
        uint4 v = mbase[r * 256];
        cm.x |= v.x; cm.y |= v.y; cm.z |= v.z; cm.w |= v.w;
        if ((v.x | v.y) | (v.z | v.w)) {
            miny = min(miny, r);
            maxy = max(maxy, r);
        }
        fc0 += __uint_as_float(v.x);
        fc1 += __uint_as_float(v.y);
        fc2 += __uint_as_float(v.z);
        fc3 += __uint_as_float(v.w);
    }

    int cnt = (int)((fc0 + fc1) + (fc2 + fc3));
    unsigned mbits =  (unsigned)(cm.x != 0u)
                   | ((unsigned)(cm.y != 0u) << 1)
                   | ((unsigned)(cm.z != 0u) << 2)
                   | ((unsigned)(cm.w != 0u) << 3);
    int minx, maxx;
    if (mbits) { minx = colbase + (__ffs(mbits) - 1); maxx = colbase + (31 - __clz(mbits)); }
    else       { minx = INT_MAX;                      maxx = -1; }

    // ---- single block reduction ----
    #pragma unroll
    for (int off = 16; off > 0; off >>= 1) {
        minx = min(minx, __shfl_down_sync(0xFFFFFFFFu, minx, off));
        miny = min(miny, __shfl_down_sync(0xFFFFFFFFu, miny, off));
        maxx = max(maxx, __shfl_down_sync(0xFFFFFFFFu, maxx, off));
        maxy = max(maxy, __shfl_down_sync(0xFFFFFFFFu, maxy, off));
        cnt +=           __shfl_down_sync(0xFFFFFFFFu, cnt,  off);
    }

    __shared__ int s_minx[8], s_miny[8], s_maxx[8], s_maxy[8], s_cnt[8];
    if (lane == 0) {
        s_minx[wid] = minx; s_miny[wid] = miny;
        s_maxx[wid] = maxx; s_maxy[wid] = maxy;
        s_cnt [wid] = cnt;
    }
    __syncthreads();

    // Warp 0: publish partial, arrive on per-mask counter; the 19th block
    // of each mask reduces that mask's partials and writes its bbox.
    if (wid == 0) {
        unsigned pos = 0;
        if (lane == 0) {
            int bminx = s_minx[0], bminy = s_miny[0];
            int bmaxx = s_maxx[0], bmaxy = s_maxy[0];
            int bcnt  = s_cnt[0];
            #pragma unroll
            for (int j = 1; j < NTHREADS / 32; j++) {
                bminx = min(bminx, s_minx[j]);
                bminy = min(bminy, s_miny[j]);
                bmaxx = max(bmaxx, s_maxx[j]);
                bmaxy = max(bmaxy, s_maxy[j]);
                bcnt += s_cnt[j];
            }
            g_pminx[blockIdx.x] = bminx;
            g_pminy[blockIdx.x] = bminy;
            g_pmaxx[blockIdx.x] = bmaxx;
            g_pmaxy[blockIdx.x] = bmaxy;
            g_pcnt [blockIdx.x] = bcnt;
            __threadfence();   // partials visible before arrival
            pos = atomicAdd(&g_marrive[mask], 1u);
        }
        pos = __shfl_sync(0xFFFFFFFFu, pos, 0);

        if (pos == BLOCKS_PER_MASK - 1) {
            __threadfence();   // acquire: see all partials of this mask
            int fminx = INT_MAX, fminy = INT_MAX, fmaxx = -1, fmaxy = -1, fcnt = 0;
            if (lane < BLOCKS_PER_MASK) {
                const int idx = mask * BLOCKS_PER_MASK + lane;
                fminx = g_pminx[idx];
                fminy = g_pminy[idx];
                fmaxx = g_pmaxx[idx];
                fmaxy = g_pmaxy[idx];
                fcnt  = g_pcnt [idx];
            }
            #pragma unroll
            for (int off = 16; off > 0; off >>= 1) {
                fminx = min(fminx, __shfl_down_sync(0xFFFFFFFFu, fminx, off));
                fminy = min(fminy, __shfl_down_sync(0xFFFFFFFFu, fminy, off));
                fmaxx = max(fmaxx, __shfl_down_sync(0xFFFFFFFFu, fmaxx, off));
                fmaxy = max(fmaxy, __shfl_down_sync(0xFFFFFFFFu, fmaxy, off));
                fcnt +=            __shfl_down_sync(0xFFFFFFFFu, fcnt,  off);
            }
            if (lane == 0) {
                float4 b = (fcnt > AREA_THRESH)
                    ? make_float4((float)fminx, (float)fminy, (float)fmaxx, (float)fmaxy)
                    : make_float4(0.f, 0.f, 0.f, 0.f);
                reinterpret_cast<float4*>(out)[mask] = b;
                g_marrive[mask] = 0;   // reset for next graph replay
            }
        }
    }
}

extern "C" void kernel_launch(void* const* d_in, const int* in_sizes, int n_in,
                              void* d_out, int out_size) {
    const float* masks = (const float*)d_in[0];
    float* out = (float*)d_out;
    fsam_fused_kernel<<<GRID, NTHREADS>>>(masks, out);
}